// round 3
// baseline (speedup 1.0000x reference)
#include <cuda_runtime.h>
#include <cuda_bf16.h>
#include <cstdint>

// LocallyConnected2d: out[b,o,y,x] = sum_{c,k} x[b,c,y+i,x+j] * w[o,c,y,x,k]
// B=16, C_IN=16, C_OUT=16, H=W=64, OH=OW=62, K=3x3.
//
// R3: 4 blocks/SM (single wave for all 496 blocks) + triple-buffered cp.async
// with ONE barrier per channel. c-split 2 via grid z, combined with atomicAdd
// into a zeroed buffer (2 commutative contributions -> deterministic).

#define B_  16
#define CIN 16
#define CO  16
#define H_  64
#define W_  64
#define OH_ 62
#define OW_ 62
#define TX  16            // x-positions per block
#define NC  8             // channels per block (2-way c split)

#define WR  18            // weight smem row stride: [r = xl*9+k][o]
#define XS  60            // x smem batch stride: [b][r*18+cc]
#define WBUF (TX * 9 * WR)   // 2592 floats per buffer
#define XBUF (B_ * XS)       // 960 floats per buffer

#define WCSTRIDE (OH_ * OW_ * 9)  // weight float stride per c: 34596
#define XCSTRIDE (H_ * W_)        // x float stride per c: 4096

__device__ __forceinline__ void ffma2(unsigned long long& d,
                                      unsigned long long a,
                                      unsigned long long b) {
    asm("fma.rn.f32x2 %0, %1, %2, %0;" : "+l"(d) : "l"(a), "l"(b));
}

__device__ __forceinline__ unsigned long long bcast2(float v) {
    unsigned long long p;
    asm("mov.b64 %0, {%1, %1};" : "=l"(p) : "f"(v));
    return p;
}

__device__ __forceinline__ void cp_async4(uint32_t dst, const float* src, int sz) {
    asm volatile("cp.async.ca.shared.global [%0], [%1], 4, %2;\n"
                 :: "r"(dst), "l"(src), "r"(sz));
}

__global__ void zero_kernel(float* p, int n) {
    for (int i = blockIdx.x * blockDim.x + threadIdx.x; i < n;
         i += gridDim.x * blockDim.x)
        p[i] = 0.0f;
}

__global__ __launch_bounds__(256, 4)
void lc2d_kernel(const float* __restrict__ xin,
                 const float* __restrict__ wgt,
                 float* __restrict__ out) {
    __shared__ float sh_w[3 * WBUF];
    __shared__ float sh_x[3 * XBUF];

    const int tid  = threadIdx.x;
    const int xl   = tid & 15;     // x position within tile
    const int slot = tid >> 4;     // 0..15
    const int sb   = slot & 3;     // batch group
    const int ob   = slot >> 2;    // out-chan group

    const int y  = blockIdx.y;
    const int x0 = blockIdx.x * TX;
    const int xt = min(TX, OW_ - x0);   // 16 or 14
    const int xt9 = xt * 9;
    const int c0 = blockIdx.z * NC;

    const uint32_t shw_base = (uint32_t)__cvta_generic_to_shared(sh_w);
    const uint32_t shx_base = (uint32_t)__cvta_generic_to_shared(sh_x);

    // ---- staging descriptors (computed once) ----
    // weight: thread handles o = tid>>4, elements q = (tid&15) + 16n, n=0..8
    const int o_w = tid >> 4;
    const int qb  = tid & 15;
    const float* ws = wgt + ((((o_w * CIN + c0) * OH_ + y) * OW_ + x0) * 9) + qb;

    // x: thread handles b = tid>>4, elements rem = (tid&15) + 16n, n=0..3
    const int b_x = tid >> 4;
    const int jx  = tid & 15;
    int xoff[4], xsz[4];
    #pragma unroll
    for (int n = 0; n < 4; ++n) {
        int rem = jx + 16 * n;
        int r   = rem / 18;
        int cc  = rem - r * 18;
        bool ok = (rem < 54) && (x0 + cc < W_);
        xoff[n] = ok ? (r * W_ + cc) : 0;
        xsz[n]  = ok ? 4 : 0;
    }
    const float* xsb = xin + ((b_x * CIN + c0) * H_ + y) * W_ + x0;

    unsigned long long acc[4][2];
    #pragma unroll
    for (int bb = 0; bb < 4; ++bb) { acc[bb][0] = 0ull; acc[bb][1] = 0ull; }

    // ---- stage one channel's tiles into buffer `buf` (0..2) ----
    auto stage = [&](int buf, int ci) {
        const float* wsp = ws + ci * WCSTRIDE;
        const float* xsp = xsb + ci * XCSTRIDE;
        uint32_t wb = shw_base + buf * (WBUF * 4);
        #pragma unroll
        for (int n = 0; n < 9; ++n) {
            int q = qb + 16 * n;
            bool ok = q < xt9;
            cp_async4(wb + (uint32_t)(q * WR + o_w) * 4,
                      ok ? (wsp + 16 * n) : wgt, ok ? 4 : 0);
        }
        uint32_t xb = shx_base + buf * (XBUF * 4);
        #pragma unroll
        for (int n = 0; n < 4; ++n) {
            int rem = jx + 16 * n;
            if (rem < 54)
                cp_async4(xb + (uint32_t)(b_x * XS + rem) * 4,
                          xsp + xoff[n], xsz[n]);
        }
        asm volatile("cp.async.commit_group;\n" ::: "memory");
    };

    // prologue: two channels in flight
    stage(0, 0);
    stage(1, 1);

    int rd = 0;         // buffer to read this iteration
    #pragma unroll 1
    for (int ci = 0; ci < NC; ++ci) {
        if (ci < NC - 1) {
            asm volatile("cp.async.wait_group 1;\n" ::: "memory");
        } else {
            asm volatile("cp.async.wait_group 0;\n" ::: "memory");
        }
        __syncthreads();   // all threads' copies for buf `rd` complete;
                           // also: all warps finished reading buf (rd+2)%3

        if (ci + 2 < NC) {
            int st = rd - 1; if (st < 0) st += 3;   // (rd+2)%3
            stage(st, ci + 2);
        }

        const float* swb = sh_w + rd * WBUF;
        const float* sxb = sh_x + rd * XBUF;

        #pragma unroll
        for (int k = 0; k < 9; ++k) {
            const int i = k / 3;
            const int j = k - i * 3;
            const float* wp = &swb[(xl * 9 + k) * WR + ob * 4];
            unsigned long long wv0 = *reinterpret_cast<const unsigned long long*>(wp);
            unsigned long long wv1 = *reinterpret_cast<const unsigned long long*>(wp + 2);
            #pragma unroll
            for (int bb = 0; bb < 4; ++bb) {
                float xs_v = sxb[(sb * 4 + bb) * XS + i * 18 + xl + j];
                unsigned long long xp = bcast2(xs_v);
                ffma2(acc[bb][0], xp, wv0);
                ffma2(acc[bb][1], xp, wv1);
            }
        }

        ++rd; if (rd == 3) rd = 0;
    }

    // ---- combine: exactly 2 contributions per output (c halves) ----
    if (xl < xt) {
        #pragma unroll
        for (int bb = 0; bb < 4; ++bb) {
            const int b = sb * 4 + bb;
            #pragma unroll
            for (int p = 0; p < 2; ++p) {
                float lo, hi;
                asm("mov.b64 {%0, %1}, %2;" : "=f"(lo), "=f"(hi) : "l"(acc[bb][p]));
                const int o = ob * 4 + p * 2;
                atomicAdd(&out[((b * CO + o)     * OH_ + y) * OW_ + x0 + xl], lo);
                atomicAdd(&out[((b * CO + o + 1) * OH_ + y) * OW_ + x0 + xl], hi);
            }
        }
    }
}

extern "C" void kernel_launch(void* const* d_in, const int* in_sizes, int n_in,
                              void* d_out, int out_size) {
    const float* x = (const float*)d_in[0];
    const float* w = (const float*)d_in[1];
    float* out = (float*)d_out;

    zero_kernel<<<240, 256>>>(out, out_size);

    dim3 grid((OW_ + TX - 1) / TX, OH_, 2);   // (4, 62, 2) = 496 blocks
    lc2d_kernel<<<grid, 256>>>(x, w, out);
}

// round 4
// speedup vs baseline: 1.0894x; 1.0894x over previous
#include <cuda_runtime.h>
#include <cuda_bf16.h>
#include <cstdint>

// LocallyConnected2d: out[b,o,y,x] = sum_{c,k} x[b,c,y+i,x+j] * w[o,c,y,x,k]
// B=16, C_IN=16, C_OUT=16, H=W=64, OH=OW=62, K=3x3.
//
// R4: weight kept in natural [o][144] smem layout -> staged with 16B cp.async
// (uniform alignment shift sh=2*(y&1)). x staged into b-pair-interleaved
// layout so compute uses LDS.64 pairs + w broadcast via FFMA2 over b-pairs.
// Triple-buffered, one barrier/channel, 2-way c-split + atomicAdd (2
// commutative contributions -> deterministic).

#define B_  16
#define CIN 16
#define CO  16
#define H_  64
#define W_  64
#define OH_ 62
#define OW_ 62
#define TX  16

#define NC  8                       // channels per block (2-way c split)
#define WROW 148                    // weight smem row stride (floats, 16B mult)
#define WBUF (CO * WROW)            // 2368 floats
#define XBUF (8 * 3 * 40)           // 960 floats: [bpair][row][20 cols x 2]

#define WOSTRIDE (CIN * OH_ * OW_ * 9)   // weight float stride per o: 553536
#define WCSTRIDE (OH_ * OW_ * 9)         // weight float stride per c: 34596
#define XCSTRIDE (H_ * W_)               // x float stride per c: 4096

__device__ __forceinline__ void ffma2(unsigned long long& d,
                                      unsigned long long a,
                                      unsigned long long b) {
    asm("fma.rn.f32x2 %0, %1, %2, %0;" : "+l"(d) : "l"(a), "l"(b));
}

__device__ __forceinline__ unsigned long long bcast2(float v) {
    unsigned long long p;
    asm("mov.b64 %0, {%1, %1};" : "=l"(p) : "f"(v));
    return p;
}

__device__ __forceinline__ void cp_async16(uint32_t dst, const float* src) {
    asm volatile("cp.async.cg.shared.global [%0], [%1], 16;\n"
                 :: "r"(dst), "l"(src));
}

__device__ __forceinline__ void cp_async4(uint32_t dst, const float* src, int sz) {
    asm volatile("cp.async.ca.shared.global [%0], [%1], 4, %2;\n"
                 :: "r"(dst), "l"(src), "r"(sz));
}

__global__ void zero_kernel(float* p, int n) {
    for (int i = blockIdx.x * blockDim.x + threadIdx.x; i < n;
         i += gridDim.x * blockDim.x)
        p[i] = 0.0f;
}

__global__ __launch_bounds__(256, 4)
void lc2d_kernel(const float* __restrict__ xin,
                 const float* __restrict__ wgt,
                 float* __restrict__ out) {
    __shared__ __align__(16) float sh_w[3 * WBUF];
    __shared__ __align__(16) float sh_x[3 * XBUF];

    const int tid  = threadIdx.x;
    const int xl   = tid & 15;
    const int slot = tid >> 4;
    const int sb   = slot & 3;     // batch group: b = sb*4 + ...
    const int ob   = slot >> 2;    // out-chan group: o = ob*4 + ...

    const int y  = blockIdx.y;
    const int x0 = blockIdx.x * TX;
    const int xt = min(TX, OW_ - x0);       // 16 or 14
    const int c0 = blockIdx.z * NC;
    const int sh = 2 * (y & 1);             // uniform 16B-alignment shift

    const uint32_t shw_base = (uint32_t)__cvta_generic_to_shared(sh_w);
    const uint32_t shx_base = (uint32_t)__cvta_generic_to_shared(sh_x);

    // ---- weight staging descriptors (16B chunks), computed once ----
    const int rowch  = (xt == TX) ? 37 : 32;    // 16B chunks per o-row
    const int nchunk = CO * rowch;
    // aligned c-base: subtract uniform shift
    const float* wcbase = wgt + (((c0 * OH_ + y) * OW_ + x0) * 9) - sh;

    const float* wsrc[3];
    uint32_t     wdst[3];
    bool         wok[3];
    #pragma unroll
    for (int n = 0; n < 3; ++n) {
        int m = tid + 256 * n;
        wok[n] = (m < nchunk);
        int o   = m / rowch;
        int ci4 = (m - o * rowch) * 4;
        if (o > 15) { o = 15; ci4 = 0; }        // keep addresses sane when !wok
        wsrc[n] = wcbase + o * WOSTRIDE + ci4;
        wdst[n] = (uint32_t)(o * WROW + ci4) * 4;
    }

    // ---- x staging descriptors (4B, b-pair interleaved), computed once ----
    const int b_x = tid >> 4;
    const int jx  = tid & 15;
    const float* xsb = xin + ((b_x * CIN + c0) * H_ + y) * W_ + x0;
    int      xsrcoff[4], xsz[4];
    uint32_t xdst[4];
    bool     xvalid[4];
    #pragma unroll
    for (int n = 0; n < 4; ++n) {
        int rem = jx + 16 * n;
        xvalid[n] = (rem < 54);
        int r  = rem / 18;
        int cc = rem - r * 18;
        bool ok = xvalid[n] && (x0 + cc < W_);
        xsrcoff[n] = ok ? (r * W_ + cc) : 0;
        xsz[n]     = ok ? 4 : 0;
        xdst[n] = (uint32_t)((b_x >> 1) * 120 + r * 40 + cc * 2 + (b_x & 1)) * 4;
    }

    unsigned long long acc[4][2];
    #pragma unroll
    for (int oo = 0; oo < 4; ++oo) { acc[oo][0] = 0ull; acc[oo][1] = 0ull; }

    auto stage = [&](int buf, int ci) {
        uint32_t wb = shw_base + (uint32_t)buf * (WBUF * 4);
        #pragma unroll
        for (int n = 0; n < 3; ++n)
            if (wok[n]) cp_async16(wb + wdst[n], wsrc[n] + ci * WCSTRIDE);
        uint32_t xb = shx_base + (uint32_t)buf * (XBUF * 4);
        #pragma unroll
        for (int n = 0; n < 4; ++n)
            if (xvalid[n])
                cp_async4(xb + xdst[n], xsb + ci * XCSTRIDE + xsrcoff[n], xsz[n]);
        asm volatile("cp.async.commit_group;\n" ::: "memory");
    };

    // prologue: two channels in flight
    stage(0, 0);
    stage(1, 1);

    int rd = 0;
    #pragma unroll 1
    for (int ci = 0; ci < NC; ++ci) {
        if (ci < NC - 1) {
            asm volatile("cp.async.wait_group 1;\n" ::: "memory");
        } else {
            asm volatile("cp.async.wait_group 0;\n" ::: "memory");
        }
        __syncthreads();

        if (ci + 2 < NC) {
            int st = rd - 1; if (st < 0) st += 3;   // (rd+2)%3
            stage(st, ci + 2);
        }

        const float* swb = sh_w + rd * WBUF + sh;   // fold shift in
        const float* sxb = sh_x + rd * XBUF;

        #pragma unroll
        for (int k = 0; k < 9; ++k) {
            const int i = k / 3;
            const int j = k - i * 3;
            // packed x pairs {x[b], x[b+1]} via LDS.64
            unsigned long long xp0 = *reinterpret_cast<const unsigned long long*>(
                &sxb[(sb * 2)     * 120 + i * 40 + (xl + j) * 2]);
            unsigned long long xp1 = *reinterpret_cast<const unsigned long long*>(
                &sxb[(sb * 2 + 1) * 120 + i * 40 + (xl + j) * 2]);
            #pragma unroll
            for (int oo = 0; oo < 4; ++oo) {
                float wv = swb[(ob * 4 + oo) * WROW + xl * 9 + k];
                unsigned long long wb2 = bcast2(wv);
                ffma2(acc[oo][0], xp0, wb2);
                ffma2(acc[oo][1], xp1, wb2);
            }
        }

        ++rd; if (rd == 3) rd = 0;
    }

    // ---- combine: exactly 2 contributions per output (c halves) ----
    if (xl < xt) {
        #pragma unroll
        for (int oo = 0; oo < 4; ++oo) {
            const int o = ob * 4 + oo;
            #pragma unroll
            for (int bpl = 0; bpl < 2; ++bpl) {
                float lo, hi;
                asm("mov.b64 {%0, %1}, %2;" : "=f"(lo), "=f"(hi) : "l"(acc[oo][bpl]));
                const int b = sb * 4 + bpl * 2;
                atomicAdd(&out[((b * CO + o)       * OH_ + y) * OW_ + x0 + xl], lo);
                atomicAdd(&out[(((b + 1) * CO + o) * OH_ + y) * OW_ + x0 + xl], hi);
            }
        }
    }
}

extern "C" void kernel_launch(void* const* d_in, const int* in_sizes, int n_in,
                              void* d_out, int out_size) {
    const float* x = (const float*)d_in[0];
    const float* w = (const float*)d_in[1];
    float* out = (float*)d_out;

    zero_kernel<<<240, 256>>>(out, out_size);

    dim3 grid((OW_ + TX - 1) / TX, OH_, 2);   // (4, 62, 2) = 496 blocks
    lc2d_kernel<<<grid, 256>>>(x, w, out);
}

// round 5
// speedup vs baseline: 1.2073x; 1.1082x over previous
#include <cuda_runtime.h>
#include <cuda_bf16.h>
#include <cstdint>

// LocallyConnected2d: out[b,o,y,x] = sum_{c,k} x[b,c,y+i,x+j] * w[o,c,y,x,k]
// B=16, C_IN=16, C_OUT=16, H=W=64, OH=OW=62, K=3x3.
//
// R5: c-split 4 (992 blocks -> solid 4 blocks/SM in wave 1) with the R4 block
// structure unchanged: 16B cp.async weight staging into natural [o][144]
// layout, b-pair-interleaved x, FFMA2 over b-pairs, triple-buffered, one
// barrier per channel. 4 atomicAdd contributions into zeroed output.

#define B_  16
#define CIN 16
#define CO  16
#define H_  64
#define W_  64
#define OH_ 62
#define OW_ 62
#define TX  16

#define NC  4                       // channels per block (4-way c split)
#define WROW 148                    // weight smem row stride (floats, 16B mult)
#define WBUF (CO * WROW)            // 2368 floats
#define XBUF (8 * 3 * 40)           // 960 floats: [bpair][row][20 cols x 2]

#define WOSTRIDE (CIN * OH_ * OW_ * 9)   // weight float stride per o: 553536
#define WCSTRIDE (OH_ * OW_ * 9)         // weight float stride per c: 34596
#define XCSTRIDE (H_ * W_)               // x float stride per c: 4096

__device__ __forceinline__ void ffma2(unsigned long long& d,
                                      unsigned long long a,
                                      unsigned long long b) {
    asm("fma.rn.f32x2 %0, %1, %2, %0;" : "+l"(d) : "l"(a), "l"(b));
}

__device__ __forceinline__ unsigned long long bcast2(float v) {
    unsigned long long p;
    asm("mov.b64 %0, {%1, %1};" : "=l"(p) : "f"(v));
    return p;
}

__device__ __forceinline__ void cp_async16(uint32_t dst, const float* src) {
    asm volatile("cp.async.cg.shared.global [%0], [%1], 16;\n"
                 :: "r"(dst), "l"(src));
}

__device__ __forceinline__ void cp_async4(uint32_t dst, const float* src, int sz) {
    asm volatile("cp.async.ca.shared.global [%0], [%1], 4, %2;\n"
                 :: "r"(dst), "l"(src), "r"(sz));
}

__global__ void zero_kernel(float* p, int n) {
    for (int i = blockIdx.x * blockDim.x + threadIdx.x; i < n;
         i += gridDim.x * blockDim.x)
        p[i] = 0.0f;
}

__global__ __launch_bounds__(256, 4)
void lc2d_kernel(const float* __restrict__ xin,
                 const float* __restrict__ wgt,
                 float* __restrict__ out) {
    __shared__ __align__(16) float sh_w[3 * WBUF];
    __shared__ __align__(16) float sh_x[3 * XBUF];

    const int tid  = threadIdx.x;
    const int xl   = tid & 15;
    const int slot = tid >> 4;
    const int sb   = slot & 3;     // batch group: b = sb*4 + ...
    const int ob   = slot >> 2;    // out-chan group: o = ob*4 + ...

    const int y  = blockIdx.y;
    const int x0 = blockIdx.x * TX;
    const int xt = min(TX, OW_ - x0);       // 16 or 14
    const int c0 = blockIdx.z * NC;
    const int sh = 2 * (y & 1);             // uniform 16B-alignment shift

    const uint32_t shw_base = (uint32_t)__cvta_generic_to_shared(sh_w);
    const uint32_t shx_base = (uint32_t)__cvta_generic_to_shared(sh_x);

    // ---- weight staging descriptors (16B chunks), computed once ----
    const int rowch  = (xt == TX) ? 37 : 32;    // 16B chunks per o-row
    const int nchunk = CO * rowch;
    const float* wcbase = wgt + (((c0 * OH_ + y) * OW_ + x0) * 9) - sh;

    const float* wsrc[3];
    uint32_t     wdst[3];
    bool         wok[3];
    #pragma unroll
    for (int n = 0; n < 3; ++n) {
        int m = tid + 256 * n;
        wok[n] = (m < nchunk);
        int o   = m / rowch;
        int ci4 = (m - o * rowch) * 4;
        if (o > 15) { o = 15; ci4 = 0; }
        wsrc[n] = wcbase + o * WOSTRIDE + ci4;
        wdst[n] = (uint32_t)(o * WROW + ci4) * 4;
    }

    // ---- x staging descriptors (4B, b-pair interleaved), computed once ----
    const int b_x = tid >> 4;
    const int jx  = tid & 15;
    const float* xsb = xin + ((b_x * CIN + c0) * H_ + y) * W_ + x0;
    int      xsrcoff[4], xsz[4];
    uint32_t xdst[4];
    bool     xvalid[4];
    #pragma unroll
    for (int n = 0; n < 4; ++n) {
        int rem = jx + 16 * n;
        xvalid[n] = (rem < 54);
        int r  = rem / 18;
        int cc = rem - r * 18;
        bool ok = xvalid[n] && (x0 + cc < W_);
        xsrcoff[n] = ok ? (r * W_ + cc) : 0;
        xsz[n]     = ok ? 4 : 0;
        xdst[n] = (uint32_t)((b_x >> 1) * 120 + r * 40 + cc * 2 + (b_x & 1)) * 4;
    }

    unsigned long long acc[4][2];
    #pragma unroll
    for (int oo = 0; oo < 4; ++oo) { acc[oo][0] = 0ull; acc[oo][1] = 0ull; }

    auto stage = [&](int buf, int ci) {
        uint32_t wb = shw_base + (uint32_t)buf * (WBUF * 4);
        #pragma unroll
        for (int n = 0; n < 3; ++n)
            if (wok[n]) cp_async16(wb + wdst[n], wsrc[n] + ci * WCSTRIDE);
        uint32_t xb = shx_base + (uint32_t)buf * (XBUF * 4);
        #pragma unroll
        for (int n = 0; n < 4; ++n)
            if (xvalid[n])
                cp_async4(xb + xdst[n], xsb + ci * XCSTRIDE + xsrcoff[n], xsz[n]);
        asm volatile("cp.async.commit_group;\n" ::: "memory");
    };

    // prologue: two channels in flight
    stage(0, 0);
    stage(1, 1);

    int rd = 0;
    #pragma unroll 1
    for (int ci = 0; ci < NC; ++ci) {
        if (ci < NC - 1) {
            asm volatile("cp.async.wait_group 1;\n" ::: "memory");
        } else {
            asm volatile("cp.async.wait_group 0;\n" ::: "memory");
        }
        __syncthreads();

        if (ci + 2 < NC) {
            int st = rd - 1; if (st < 0) st += 3;   // (rd+2)%3
            stage(st, ci + 2);
        }

        const float* swb = sh_w + rd * WBUF + sh;   // fold alignment shift in
        const float* sxb = sh_x + rd * XBUF;

        #pragma unroll
        for (int k = 0; k < 9; ++k) {
            const int i = k / 3;
            const int j = k - i * 3;
            unsigned long long xp0 = *reinterpret_cast<const unsigned long long*>(
                &sxb[(sb * 2)     * 120 + i * 40 + (xl + j) * 2]);
            unsigned long long xp1 = *reinterpret_cast<const unsigned long long*>(
                &sxb[(sb * 2 + 1) * 120 + i * 40 + (xl + j) * 2]);
            #pragma unroll
            for (int oo = 0; oo < 4; ++oo) {
                float wv = swb[(ob * 4 + oo) * WROW + xl * 9 + k];
                unsigned long long wb2 = bcast2(wv);
                ffma2(acc[oo][0], xp0, wb2);
                ffma2(acc[oo][1], xp1, wb2);
            }
        }

        ++rd; if (rd == 3) rd = 0;
    }

    // ---- combine: 4 contributions per output (c quarters) ----
    if (xl < xt) {
        #pragma unroll
        for (int oo = 0; oo < 4; ++oo) {
            const int o = ob * 4 + oo;
            #pragma unroll
            for (int bpl = 0; bpl < 2; ++bpl) {
                float lo, hi;
                asm("mov.b64 {%0, %1}, %2;" : "=f"(lo), "=f"(hi) : "l"(acc[oo][bpl]));
                const int b = sb * 4 + bpl * 2;
                atomicAdd(&out[((b * CO + o)       * OH_ + y) * OW_ + x0 + xl], lo);
                atomicAdd(&out[(((b + 1) * CO + o) * OH_ + y) * OW_ + x0 + xl], hi);
            }
        }
    }
}

extern "C" void kernel_launch(void* const* d_in, const int* in_sizes, int n_in,
                              void* d_out, int out_size) {
    const float* x = (const float*)d_in[0];
    const float* w = (const float*)d_in[1];
    float* out = (float*)d_out;

    zero_kernel<<<240, 256>>>(out, out_size);

    dim3 grid((OW_ + TX - 1) / TX, OH_, 4);   // (4, 62, 4) = 992 blocks
    lc2d_kernel<<<grid, 256>>>(x, w, out);
}